// round 1
// baseline (speedup 1.0000x reference)
#include <cuda_runtime.h>
#include <math.h>

// ---------------------------------------------------------------------------
// Problem constants (shapes fixed by the reference)
// ---------------------------------------------------------------------------
#define BB 4
#define LL 1024
#define DD 1024
#define HH 16
#define HD 64
#define II 3280
#define NROWS (BB * LL)          // 4096
#define EPSV 1e-5f

// ---------------------------------------------------------------------------
// Scratch (single __device__ global, no allocations anywhere)
// ---------------------------------------------------------------------------
// layout (floats):
//  xn   : NROWS*DD
//  q    : NROWS*DD
//  k    : NROWS*DD
//  v    : NROWS*DD
//  attn : NROWS*DD
//  a    : NROWS*DD
//  h    : NROWS*DD
//  hn   : NROWS*DD
//  f    : NROWS*DD
//  z1   : NROWS*II
//  z3   : NROWS*II
#define SZ_D ((size_t)NROWS * DD)      // 4,194,304
#define SZ_I ((size_t)NROWS * II)      // 13,434,880
__device__ float g_scratch[9 * SZ_D + 2 * SZ_I];

// ---------------------------------------------------------------------------
// RMSNorm: one block per row. Optional residual (out = resid + norm(in)).
// Matches reference: clip to +-1e4, mean of x^2, rms = sqrt(max(mean,eps)+eps),
// out = x/rms*w, nonfinite -> 0, then + resid.
// ---------------------------------------------------------------------------
template <int W, int T>
__global__ void rmsnorm_k(const float* __restrict__ in,
                          const float* __restrict__ w,
                          const float* __restrict__ resid,
                          float* __restrict__ out)
{
    constexpr int PER = W / T;
    const size_t row = blockIdx.x;
    const float* xr = in + row * (size_t)W;
    float vals[PER];
    float ss = 0.f;
#pragma unroll
    for (int i = 0; i < PER; i++) {
        float vv = xr[threadIdx.x + i * T];
        vv = fminf(fmaxf(vv, -10000.f), 10000.f);
        vals[i] = vv;
        ss += vv * vv;
    }
    __shared__ float red[T];
    red[threadIdx.x] = ss;
    __syncthreads();
#pragma unroll
    for (int s = T / 2; s > 0; s >>= 1) {
        if (threadIdx.x < s) red[threadIdx.x] += red[threadIdx.x + s];
        __syncthreads();
    }
    const float mean = red[0] / (float)W;
    const float inv = 1.f / sqrtf(fmaxf(mean, EPSV) + EPSV);
#pragma unroll
    for (int i = 0; i < PER; i++) {
        const int c = threadIdx.x + i * T;
        float o = vals[i] * inv * w[c];
        if (!isfinite(o)) o = 0.f;
        if (resid) o += resid[row * (size_t)W + c];
        out[row * (size_t)W + c] = o;
    }
}

// ---------------------------------------------------------------------------
// SGEMM (NT): C[n,m] = sum_k A[n,k]*B[m,k] + bias[m]
// A: [N,K] row-major, B: [M,K] row-major. 128x128 tile, BK=8, 8x8/thread.
// N is always a multiple of 128; M may not be (3280) -> guarded.
// K is always a multiple of 8 and of 4 (float4 loads ok).
// ---------------------------------------------------------------------------
__global__ void __launch_bounds__(256)
gemm_nt_bias(const float* __restrict__ A, const float* __restrict__ B,
             const float* __restrict__ bias, float* __restrict__ C,
             int N, int M, int K)
{
    __shared__ float As[8][128];
    __shared__ float Bs[8][128];

    const int tid  = threadIdx.x;
    const int lrow = tid >> 1;             // 0..127
    const int lcol = (tid & 1) << 2;       // 0 or 4
    const size_t arow = (size_t)blockIdx.y * 128 + lrow;
    const size_t brow = (size_t)blockIdx.x * 128 + lrow;
    const bool bval = brow < (size_t)M;

    const float* Ap = A + arow * (size_t)K + lcol;
    const float* Bp = B + brow * (size_t)K + lcol;

    const int ty = tid >> 4;   // 0..15
    const int tx = tid & 15;   // 0..15

    float acc[8][8];
#pragma unroll
    for (int i = 0; i < 8; i++)
#pragma unroll
        for (int j = 0; j < 8; j++) acc[i][j] = 0.f;

    for (int k0 = 0; k0 < K; k0 += 8) {
        float4 a4 = *(const float4*)(Ap + k0);
        float4 b4 = bval ? *(const float4*)(Bp + k0) : make_float4(0.f, 0.f, 0.f, 0.f);
        As[lcol + 0][lrow] = a4.x; As[lcol + 1][lrow] = a4.y;
        As[lcol + 2][lrow] = a4.z; As[lcol + 3][lrow] = a4.w;
        Bs[lcol + 0][lrow] = b4.x; Bs[lcol + 1][lrow] = b4.y;
        Bs[lcol + 2][lrow] = b4.z; Bs[lcol + 3][lrow] = b4.w;
        __syncthreads();
#pragma unroll
        for (int kk = 0; kk < 8; kk++) {
            float ar[8], br[8];
#pragma unroll
            for (int i = 0; i < 8; i++) ar[i] = As[kk][ty * 8 + i];
#pragma unroll
            for (int j = 0; j < 8; j++) br[j] = Bs[kk][tx * 8 + j];
#pragma unroll
            for (int i = 0; i < 8; i++)
#pragma unroll
                for (int j = 0; j < 8; j++) acc[i][j] = fmaf(ar[i], br[j], acc[i][j]);
        }
        __syncthreads();
    }

#pragma unroll
    for (int i = 0; i < 8; i++) {
        const size_t row = (size_t)blockIdx.y * 128 + ty * 8 + i;
#pragma unroll
        for (int j = 0; j < 8; j++) {
            const int col = blockIdx.x * 128 + tx * 8 + j;
            if (col < M) C[row * (size_t)M + col] = acc[i][j] + bias[col];
        }
    }
}

// ---------------------------------------------------------------------------
// Sliding-window causal attention, one block per (b, h, query).
// Keys j in [max(0, qi - (win-1)), qi]. Softmax over <=256 scores.
// q,k,v layout: [(b*L + l)*D + h*HD + d]
// ---------------------------------------------------------------------------
__global__ void __launch_bounds__(256)
attn_kernel(const float* __restrict__ q, const float* __restrict__ k,
            const float* __restrict__ v, float* __restrict__ o,
            const int* __restrict__ winp)
{
    const int idx = blockIdx.x;
    const int qi = idx & (LL - 1);
    const int h  = (idx >> 10) & (HH - 1);
    const int b  = idx >> 14;
    const int win = winp ? *winp : 256;

    int j0 = qi - (win - 1);
    if (j0 < 0) j0 = 0;
    const int cnt = qi - j0 + 1;   // 1..256

    __shared__ float sq[HD];
    __shared__ float sc[256];
    __shared__ float red[256];
    __shared__ float s_mx, s_sum;

    const int t = threadIdx.x;
    if (t < HD) sq[t] = q[((size_t)(b * LL + qi)) * DD + h * HD + t];
    __syncthreads();

    float s = -INFINITY;
    if (t < cnt) {
        const float* kr = k + ((size_t)(b * LL + j0 + t)) * DD + h * HD;
        float acc = 0.f;
#pragma unroll
        for (int d = 0; d < HD; d++) acc = fmaf(sq[d], kr[d], acc);
        s = acc * 0.125f;   // HD^-0.5
    }
    sc[t] = s;
    red[t] = s;
    __syncthreads();
#pragma unroll
    for (int st = 128; st > 0; st >>= 1) {
        if (t < st) red[t] = fmaxf(red[t], red[t + st]);
        __syncthreads();
    }
    if (t == 0) s_mx = red[0];
    __syncthreads();

    const float p = (t < cnt) ? expf(sc[t] - s_mx) : 0.f;
    sc[t] = p;
    red[t] = p;
    __syncthreads();
#pragma unroll
    for (int st = 128; st > 0; st >>= 1) {
        if (t < st) red[t] += red[t + st];
        __syncthreads();
    }
    if (t == 0) s_sum = red[0];
    __syncthreads();

    if (t < HD) {
        const float invs = 1.f / s_sum;
        float acc = 0.f;
        for (int j = 0; j < cnt; j++)
            acc = fmaf(sc[j], v[((size_t)(b * LL + j0 + j)) * DD + h * HD + t], acc);
        float out = acc * invs;
        if (!isfinite(out)) out = 0.f;
        o[((size_t)(b * LL + qi)) * DD + h * HD + t] = out;
    }
}

// ---------------------------------------------------------------------------
// g = silu(z1) * z3
// ---------------------------------------------------------------------------
__global__ void silu_mul_k(const float* __restrict__ z1,
                           const float* __restrict__ z3,
                           float* __restrict__ g, size_t n)
{
    size_t i = (size_t)blockIdx.x * blockDim.x + threadIdx.x;
    if (i < n) {
        float a = z1[i];
        float sv = a / (1.f + expf(-a));
        g[i] = sv * z3[i];
    }
}

// ---------------------------------------------------------------------------
// Launch
// ---------------------------------------------------------------------------
extern "C" void kernel_launch(void* const* d_in, const int* in_sizes, int n_in,
                              void* d_out, int out_size)
{
    const float* x    = (const float*)d_in[0];
    const float* wq_w = (const float*)d_in[1];
    const float* wq_b = (const float*)d_in[2];
    const float* wk_w = (const float*)d_in[3];
    const float* wk_b = (const float*)d_in[4];
    const float* wv_w = (const float*)d_in[5];
    const float* wv_b = (const float*)d_in[6];
    const float* wo_w = (const float*)d_in[7];
    const float* wo_b = (const float*)d_in[8];
    const float* q_nw = (const float*)d_in[9];
    const float* k_nw = (const float*)d_in[10];
    const float* s_nw = (const float*)d_in[11];
    const float* sp_nw= (const float*)d_in[12];
    const float* f_nw = (const float*)d_in[13];
    const float* fp_nw= (const float*)d_in[14];
    const float* w1_w = (const float*)d_in[15];
    const float* w1_b = (const float*)d_in[16];
    const float* w2_w = (const float*)d_in[17];
    const float* w2_b = (const float*)d_in[18];
    const float* w3_w = (const float*)d_in[19];
    const float* w3_b = (const float*)d_in[20];
    const int*   winp = (n_in > 21) ? (const int*)d_in[21] : nullptr;

    float* base = nullptr;
    cudaGetSymbolAddress((void**)&base, g_scratch);
    float* xn   = base + 0 * SZ_D;
    float* q    = base + 1 * SZ_D;
    float* k    = base + 2 * SZ_D;
    float* v    = base + 3 * SZ_D;
    float* attn = base + 4 * SZ_D;
    float* a    = base + 5 * SZ_D;
    float* h    = base + 6 * SZ_D;
    float* hn   = base + 7 * SZ_D;
    float* f    = base + 8 * SZ_D;
    float* z1   = base + 9 * SZ_D;
    float* z3   = base + 9 * SZ_D + SZ_I;

    float* out = (float*)d_out;

    // 1) xn = rmsnorm(x, seq_norm_w)
    rmsnorm_k<DD, 256><<<NROWS, 256>>>(x, s_nw, nullptr, xn);

    // 2) QKV projections
    {
        dim3 grid(DD / 128, NROWS / 128);
        gemm_nt_bias<<<grid, 256>>>(xn, wq_w, wq_b, q, NROWS, DD, DD);
        gemm_nt_bias<<<grid, 256>>>(xn, wk_w, wk_b, k, NROWS, DD, DD);
        gemm_nt_bias<<<grid, 256>>>(xn, wv_w, wv_b, v, NROWS, DD, DD);
    }

    // 3) per-head q/k rmsnorm (in-place)
    rmsnorm_k<HD, 64><<<NROWS * HH, 64>>>(q, q_nw, nullptr, q);
    rmsnorm_k<HD, 64><<<NROWS * HH, 64>>>(k, k_nw, nullptr, k);

    // 4) sliding-window attention
    attn_kernel<<<BB * HH * LL, 256>>>(q, k, v, attn, winp);

    // 5) output projection
    {
        dim3 grid(DD / 128, NROWS / 128);
        gemm_nt_bias<<<grid, 256>>>(attn, wo_w, wo_b, a, NROWS, DD, DD);
    }

    // 6) h = x + rmsnorm(a, seq_post_norm_w)
    rmsnorm_k<DD, 256><<<NROWS, 256>>>(a, sp_nw, x, h);

    // 7) hn = rmsnorm(h, ffn_norm_w)
    rmsnorm_k<DD, 256><<<NROWS, 256>>>(h, f_nw, nullptr, hn);

    // 8) z1 = hn @ w1^T + b1 ; z3 = hn @ w3^T + b3
    {
        dim3 grid((II + 127) / 128, NROWS / 128);
        gemm_nt_bias<<<grid, 256>>>(hn, w1_w, w1_b, z1, NROWS, II, DD);
        gemm_nt_bias<<<grid, 256>>>(hn, w3_w, w3_b, z3, NROWS, II, DD);
    }

    // 9) z1 = silu(z1) * z3
    {
        size_t n = (size_t)NROWS * II;
        int threads = 256;
        int blocks = (int)((n + threads - 1) / threads);
        silu_mul_k<<<blocks, threads>>>(z1, z3, z1, n);
    }

    // 10) f = g @ w2^T + b2
    {
        dim3 grid(DD / 128, NROWS / 128);
        gemm_nt_bias<<<grid, 256>>>(z1, w2_w, w2_b, f, NROWS, DD, II);
    }

    // 11) out = h + rmsnorm(f, ffn_post_norm_w)
    rmsnorm_k<DD, 256><<<NROWS, 256>>>(f, fp_nw, h, out);
}

// round 2
// speedup vs baseline: 1.9551x; 1.9551x over previous
#include <cuda_runtime.h>
#include <math.h>

// ---------------------------------------------------------------------------
// Problem constants
// ---------------------------------------------------------------------------
#define BB 4
#define LL 1024
#define DD 1024
#define HH 16
#define HD 64
#define II 3280
#define NROWS (BB * LL)
#define EPSV 1e-5f

#define SZ_D ((size_t)NROWS * DD)
#define SZ_I ((size_t)NROWS * II)
__device__ float g_scratch[9 * SZ_D + 2 * SZ_I];

// ---------------------------------------------------------------------------
// RMSNorm
// ---------------------------------------------------------------------------
template <int W, int T>
__global__ void rmsnorm_k(const float* __restrict__ in,
                          const float* __restrict__ w,
                          const float* __restrict__ resid,
                          float* __restrict__ out)
{
    constexpr int PER = W / T;
    const size_t row = blockIdx.x;
    const float* xr = in + row * (size_t)W;
    float vals[PER];
    float ss = 0.f;
#pragma unroll
    for (int i = 0; i < PER; i++) {
        float vv = xr[threadIdx.x + i * T];
        vv = fminf(fmaxf(vv, -10000.f), 10000.f);
        vals[i] = vv;
        ss += vv * vv;
    }
    __shared__ float red[T];
    red[threadIdx.x] = ss;
    __syncthreads();
#pragma unroll
    for (int s = T / 2; s > 0; s >>= 1) {
        if (threadIdx.x < s) red[threadIdx.x] += red[threadIdx.x + s];
        __syncthreads();
    }
    const float mean = red[0] / (float)W;
    const float inv = 1.f / sqrtf(fmaxf(mean, EPSV) + EPSV);
#pragma unroll
    for (int i = 0; i < PER; i++) {
        const int c = threadIdx.x + i * T;
        float o = vals[i] * inv * w[c];
        if (!isfinite(o)) o = 0.f;
        if (resid) o += resid[row * (size_t)W + c];
        out[row * (size_t)W + c] = o;
    }
}

// ---------------------------------------------------------------------------
// SGEMM (NT): C[n,m] = sum_k A[n,k]*B[m,k] + bias[m]
// ---------------------------------------------------------------------------
__global__ void __launch_bounds__(256)
gemm_nt_bias(const float* __restrict__ A, const float* __restrict__ B,
             const float* __restrict__ bias, float* __restrict__ C,
             int N, int M, int K)
{
    __shared__ float As[8][128];
    __shared__ float Bs[8][128];

    const int tid  = threadIdx.x;
    const int lrow = tid >> 1;
    const int lcol = (tid & 1) << 2;
    const size_t arow = (size_t)blockIdx.y * 128 + lrow;
    const size_t brow = (size_t)blockIdx.x * 128 + lrow;
    const bool bval = brow < (size_t)M;

    const float* Ap = A + arow * (size_t)K + lcol;
    const float* Bp = B + brow * (size_t)K + lcol;

    const int ty = tid >> 4;
    const int tx = tid & 15;

    float acc[8][8];
#pragma unroll
    for (int i = 0; i < 8; i++)
#pragma unroll
        for (int j = 0; j < 8; j++) acc[i][j] = 0.f;

    for (int k0 = 0; k0 < K; k0 += 8) {
        float4 a4 = *(const float4*)(Ap + k0);
        float4 b4 = bval ? *(const float4*)(Bp + k0) : make_float4(0.f, 0.f, 0.f, 0.f);
        As[lcol + 0][lrow] = a4.x; As[lcol + 1][lrow] = a4.y;
        As[lcol + 2][lrow] = a4.z; As[lcol + 3][lrow] = a4.w;
        Bs[lcol + 0][lrow] = b4.x; Bs[lcol + 1][lrow] = b4.y;
        Bs[lcol + 2][lrow] = b4.z; Bs[lcol + 3][lrow] = b4.w;
        __syncthreads();
#pragma unroll
        for (int kk = 0; kk < 8; kk++) {
            float ar[8], br[8];
#pragma unroll
            for (int i = 0; i < 8; i++) ar[i] = As[kk][ty * 8 + i];
#pragma unroll
            for (int j = 0; j < 8; j++) br[j] = Bs[kk][tx * 8 + j];
#pragma unroll
            for (int i = 0; i < 8; i++)
#pragma unroll
                for (int j = 0; j < 8; j++) acc[i][j] = fmaf(ar[i], br[j], acc[i][j]);
        }
        __syncthreads();
    }

#pragma unroll
    for (int i = 0; i < 8; i++) {
        const size_t row = (size_t)blockIdx.y * 128 + ty * 8 + i;
#pragma unroll
        for (int j = 0; j < 8; j++) {
            const int col = blockIdx.x * 128 + tx * 8 + j;
            if (col < M) C[row * (size_t)M + col] = acc[i][j] + bias[col];
        }
    }
}

// ---------------------------------------------------------------------------
// Tiled sliding-window attention (flash style).
// Block = (q-tile of 64, h, b). 256 threads, 16x16 grid, 4x4 register tiles.
// KV tiles of 64 keys staged in smem; K stored transposed: Kst[d][key].
// Online softmax with m/l/scale in smem.
// ---------------------------------------------------------------------------
#define ATT_SMEM_FLOATS (4 * 64 * 64 + 3 * 64)

__global__ void __launch_bounds__(256)
attn_tile_kernel(const float* __restrict__ q, const float* __restrict__ k,
                 const float* __restrict__ v, float* __restrict__ o,
                 const int* __restrict__ winp)
{
    extern __shared__ float sm[];
    float* Qs  = sm;                  // [64][64]  Qs[r][d]
    float* Kst = Qs + 64 * 64;        // [64][64]  Kst[d][key]
    float* Vs  = Kst + 64 * 64;       // [64][64]  Vs[key][d]
    float* Ss  = Vs + 64 * 64;        // [64][64]  scores -> probs
    float* m_s = Ss + 64 * 64;        // [64]
    float* l_s = m_s + 64;            // [64]
    float* sc_s = l_s + 64;           // [64]

    const int q0 = blockIdx.x * 64;
    const int h  = blockIdx.y;
    const int b  = blockIdx.z;
    const int tid = threadIdx.x;
    const int win = *winp;

    const size_t base_q = ((size_t)(b * LL + q0)) * DD + h * HD;

    // Load Q tile (coalesced float4)
    for (int i = tid; i < 1024; i += 256) {
        const int r = i >> 4;
        const int d4 = (i & 15) << 2;
        *(float4*)&Qs[r * 64 + d4] =
            *(const float4*)&q[base_q + (size_t)r * DD + d4];
    }
    if (tid < 64) { m_s[tid] = -INFINITY; l_s[tid] = 0.f; }

    const int ty = tid >> 4;
    const int tx = tid & 15;
    float accO[4][4];
#pragma unroll
    for (int i = 0; i < 4; i++)
#pragma unroll
        for (int j = 0; j < 4; j++) accO[i][j] = 0.f;

    int lo = q0 - win + 1;
    if (lo < 0) lo = 0;
    const int kt0 = lo >> 6;
    const int kt1 = q0 >> 6;

    __syncthreads();

    for (int kt = kt0; kt <= kt1; kt++) {
        const int j0 = kt << 6;
        const size_t base_k = ((size_t)(b * LL + j0)) * DD + h * HD;

        // Load K (transposed into Kst) and V
        for (int i = tid; i < 1024; i += 256) {
            const int r = i >> 4;
            const int d4 = (i & 15) << 2;
            const float4 kv = *(const float4*)&k[base_k + (size_t)r * DD + d4];
            Kst[(d4 + 0) * 64 + r] = kv.x;
            Kst[(d4 + 1) * 64 + r] = kv.y;
            Kst[(d4 + 2) * 64 + r] = kv.z;
            Kst[(d4 + 3) * 64 + r] = kv.w;
            *(float4*)&Vs[r * 64 + d4] =
                *(const float4*)&v[base_k + (size_t)r * DD + d4];
        }
        __syncthreads();

        // S = Q @ K^T
        float accS[4][4];
#pragma unroll
        for (int i = 0; i < 4; i++)
#pragma unroll
            for (int j = 0; j < 4; j++) accS[i][j] = 0.f;

        for (int d = 0; d < 64; d += 4) {
            float4 qv[4];
#pragma unroll
            for (int i = 0; i < 4; i++)
                qv[i] = *(const float4*)&Qs[(ty * 4 + i) * 64 + d];
#pragma unroll
            for (int dd = 0; dd < 4; dd++) {
                const float4 kv = *(const float4*)&Kst[(d + dd) * 64 + tx * 4];
#pragma unroll
                for (int i = 0; i < 4; i++) {
                    const float qq = ((const float*)&qv[i])[dd];
                    accS[i][0] = fmaf(qq, kv.x, accS[i][0]);
                    accS[i][1] = fmaf(qq, kv.y, accS[i][1]);
                    accS[i][2] = fmaf(qq, kv.z, accS[i][2]);
                    accS[i][3] = fmaf(qq, kv.w, accS[i][3]);
                }
            }
        }

        // Mask + scale, write to Ss
#pragma unroll
        for (int i = 0; i < 4; i++) {
            const int qi = q0 + ty * 4 + i;
#pragma unroll
            for (int j = 0; j < 4; j++) {
                const int jj = j0 + tx * 4 + j;
                const bool ok = (jj <= qi) && (qi - jj < win);
                Ss[(ty * 4 + i) * 64 + tx * 4 + j] =
                    ok ? accS[i][j] * 0.125f : -INFINITY;
            }
        }
        __syncthreads();

        // Online softmax: row = tid>>2, 4 lanes per row handle 16 cols each
        {
            const int row = tid >> 2;
            const int part = tid & 3;
            float* srow = &Ss[row * 64 + part * 16];
            float tm = -INFINITY;
#pragma unroll
            for (int c = 0; c < 16; c++) tm = fmaxf(tm, srow[c]);
            tm = fmaxf(tm, __shfl_xor_sync(0xffffffffu, tm, 1));
            tm = fmaxf(tm, __shfl_xor_sync(0xffffffffu, tm, 2));

            const float mold = m_s[row];
            const float nm = fmaxf(mold, tm);
            float scale;
            float psum = 0.f;
            if (nm == -INFINITY) {
                scale = 1.f;
#pragma unroll
                for (int c = 0; c < 16; c++) srow[c] = 0.f;
            } else {
                scale = expf(mold - nm);
#pragma unroll
                for (int c = 0; c < 16; c++) {
                    const float p = expf(srow[c] - nm);
                    srow[c] = p;
                    psum += p;
                }
            }
            psum += __shfl_xor_sync(0xffffffffu, psum, 1);
            psum += __shfl_xor_sync(0xffffffffu, psum, 2);
            if (part == 0) {
                m_s[row] = nm;
                l_s[row] = l_s[row] * scale + psum;
                sc_s[row] = scale;
            }
        }
        __syncthreads();

        // O = O*scale + P @ V
#pragma unroll
        for (int i = 0; i < 4; i++) {
            const float s = sc_s[ty * 4 + i];
#pragma unroll
            for (int j = 0; j < 4; j++) accO[i][j] *= s;
        }
        for (int kk = 0; kk < 64; kk += 4) {
            float4 pv[4];
#pragma unroll
            for (int i = 0; i < 4; i++)
                pv[i] = *(const float4*)&Ss[(ty * 4 + i) * 64 + kk];
#pragma unroll
            for (int dd = 0; dd < 4; dd++) {
                const float4 vv = *(const float4*)&Vs[(kk + dd) * 64 + tx * 4];
#pragma unroll
                for (int i = 0; i < 4; i++) {
                    const float pp = ((const float*)&pv[i])[dd];
                    accO[i][0] = fmaf(pp, vv.x, accO[i][0]);
                    accO[i][1] = fmaf(pp, vv.y, accO[i][1]);
                    accO[i][2] = fmaf(pp, vv.z, accO[i][2]);
                    accO[i][3] = fmaf(pp, vv.w, accO[i][3]);
                }
            }
        }
        __syncthreads();
    }

    // Final: divide by l, isfinite guard, write
#pragma unroll
    for (int i = 0; i < 4; i++) {
        const int r = ty * 4 + i;
        const float linv = 1.f / l_s[r];
#pragma unroll
        for (int j = 0; j < 4; j++) {
            float outv = accO[i][j] * linv;
            if (!isfinite(outv)) outv = 0.f;
            o[((size_t)(b * LL + q0 + r)) * DD + h * HD + tx * 4 + j] = outv;
        }
    }
}

// ---------------------------------------------------------------------------
// g = silu(z1) * z3
// ---------------------------------------------------------------------------
__global__ void silu_mul_k(const float* __restrict__ z1,
                           const float* __restrict__ z3,
                           float* __restrict__ g, size_t n)
{
    size_t i = (size_t)blockIdx.x * blockDim.x + threadIdx.x;
    if (i < n) {
        float a = z1[i];
        float sv = a / (1.f + expf(-a));
        g[i] = sv * z3[i];
    }
}

// ---------------------------------------------------------------------------
// Launch
// ---------------------------------------------------------------------------
extern "C" void kernel_launch(void* const* d_in, const int* in_sizes, int n_in,
                              void* d_out, int out_size)
{
    const float* x    = (const float*)d_in[0];
    const float* wq_w = (const float*)d_in[1];
    const float* wq_b = (const float*)d_in[2];
    const float* wk_w = (const float*)d_in[3];
    const float* wk_b = (const float*)d_in[4];
    const float* wv_w = (const float*)d_in[5];
    const float* wv_b = (const float*)d_in[6];
    const float* wo_w = (const float*)d_in[7];
    const float* wo_b = (const float*)d_in[8];
    const float* q_nw = (const float*)d_in[9];
    const float* k_nw = (const float*)d_in[10];
    const float* s_nw = (const float*)d_in[11];
    const float* sp_nw= (const float*)d_in[12];
    const float* f_nw = (const float*)d_in[13];
    const float* fp_nw= (const float*)d_in[14];
    const float* w1_w = (const float*)d_in[15];
    const float* w1_b = (const float*)d_in[16];
    const float* w2_w = (const float*)d_in[17];
    const float* w2_b = (const float*)d_in[18];
    const float* w3_w = (const float*)d_in[19];
    const float* w3_b = (const float*)d_in[20];
    const int*   winp = (const int*)d_in[21];

    float* base = nullptr;
    cudaGetSymbolAddress((void**)&base, g_scratch);
    float* xn   = base + 0 * SZ_D;
    float* q    = base + 1 * SZ_D;
    float* k    = base + 2 * SZ_D;
    float* v    = base + 3 * SZ_D;
    float* attn = base + 4 * SZ_D;
    float* a    = base + 5 * SZ_D;
    float* h    = base + 6 * SZ_D;
    float* hn   = base + 7 * SZ_D;
    float* f    = base + 8 * SZ_D;
    float* z1   = base + 9 * SZ_D;
    float* z3   = base + 9 * SZ_D + SZ_I;

    float* out = (float*)d_out;

    // 1) xn = rmsnorm(x, seq_norm_w)
    rmsnorm_k<DD, 256><<<NROWS, 256>>>(x, s_nw, nullptr, xn);

    // 2) QKV projections
    {
        dim3 grid(DD / 128, NROWS / 128);
        gemm_nt_bias<<<grid, 256>>>(xn, wq_w, wq_b, q, NROWS, DD, DD);
        gemm_nt_bias<<<grid, 256>>>(xn, wk_w, wk_b, k, NROWS, DD, DD);
        gemm_nt_bias<<<grid, 256>>>(xn, wv_w, wv_b, v, NROWS, DD, DD);
    }

    // 3) per-head q/k rmsnorm (in-place)
    rmsnorm_k<HD, 64><<<NROWS * HH, 64>>>(q, q_nw, nullptr, q);
    rmsnorm_k<HD, 64><<<NROWS * HH, 64>>>(k, k_nw, nullptr, k);

    // 4) tiled sliding-window attention
    {
        const size_t smem_bytes = (size_t)ATT_SMEM_FLOATS * sizeof(float);
        cudaFuncSetAttribute(attn_tile_kernel,
                             cudaFuncAttributeMaxDynamicSharedMemorySize,
                             (int)smem_bytes);
        dim3 grid(LL / 64, HH, BB);
        attn_tile_kernel<<<grid, 256, smem_bytes>>>(q, k, v, attn, winp);
    }

    // 5) output projection
    {
        dim3 grid(DD / 128, NROWS / 128);
        gemm_nt_bias<<<grid, 256>>>(attn, wo_w, wo_b, a, NROWS, DD, DD);
    }

    // 6) h = x + rmsnorm(a, seq_post_norm_w)
    rmsnorm_k<DD, 256><<<NROWS, 256>>>(a, sp_nw, x, h);

    // 7) hn = rmsnorm(h, ffn_norm_w)
    rmsnorm_k<DD, 256><<<NROWS, 256>>>(h, f_nw, nullptr, hn);

    // 8) z1/z3
    {
        dim3 grid((II + 127) / 128, NROWS / 128);
        gemm_nt_bias<<<grid, 256>>>(hn, w1_w, w1_b, z1, NROWS, II, DD);
        gemm_nt_bias<<<grid, 256>>>(hn, w3_w, w3_b, z3, NROWS, II, DD);
    }

    // 9) z1 = silu(z1) * z3
    {
        size_t n = (size_t)NROWS * II;
        silu_mul_k<<<(int)((n + 255) / 256), 256>>>(z1, z3, z1, n);
    }

    // 10) f = g @ w2^T + b2
    {
        dim3 grid(DD / 128, NROWS / 128);
        gemm_nt_bias<<<grid, 256>>>(z1, w2_w, w2_b, f, NROWS, DD, II);
    }

    // 11) out = h + rmsnorm(f, ffn_post_norm_w)
    rmsnorm_k<DD, 256><<<NROWS, 256>>>(f, fp_nw, h, out);
}

// round 3
// speedup vs baseline: 2.1864x; 1.1183x over previous
#include <cuda_runtime.h>
#include <math.h>

// ---------------------------------------------------------------------------
// Problem constants
// ---------------------------------------------------------------------------
#define BB 4
#define LL 1024
#define DD 1024
#define HH 16
#define HD 64
#define II 3280
#define NROWS (BB * LL)
#define EPSV 1e-5f

#define SZ_D ((size_t)NROWS * DD)
#define SZ_I ((size_t)NROWS * II)
__device__ float g_scratch[9 * SZ_D + 2 * SZ_I];

// ---------------------------------------------------------------------------
// RMSNorm
// ---------------------------------------------------------------------------
template <int W, int T>
__global__ void rmsnorm_k(const float* __restrict__ in,
                          const float* __restrict__ w,
                          const float* __restrict__ resid,
                          float* __restrict__ out)
{
    constexpr int PER = W / T;
    const size_t row = blockIdx.x;
    const float* xr = in + row * (size_t)W;
    float vals[PER];
    float ss = 0.f;
#pragma unroll
    for (int i = 0; i < PER; i++) {
        float vv = xr[threadIdx.x + i * T];
        vv = fminf(fmaxf(vv, -10000.f), 10000.f);
        vals[i] = vv;
        ss += vv * vv;
    }
    __shared__ float red[T];
    red[threadIdx.x] = ss;
    __syncthreads();
#pragma unroll
    for (int s = T / 2; s > 0; s >>= 1) {
        if (threadIdx.x < s) red[threadIdx.x] += red[threadIdx.x + s];
        __syncthreads();
    }
    const float mean = red[0] / (float)W;
    const float inv = 1.f / sqrtf(fmaxf(mean, EPSV) + EPSV);
#pragma unroll
    for (int i = 0; i < PER; i++) {
        const int c = threadIdx.x + i * T;
        float o = vals[i] * inv * w[c];
        if (!isfinite(o)) o = 0.f;
        if (resid) o += resid[row * (size_t)W + c];
        out[row * (size_t)W + c] = o;
    }
}

// ---------------------------------------------------------------------------
// SGEMM (NT): C[n,m] = sum_k A[n,k]*B[m,k] + bias[m]
// 128x128 tile, BK=8, 256 threads, 8x8/thread.
// Double-buffered smem + register prefetch; float4 fragment loads.
// ---------------------------------------------------------------------------
__global__ void __launch_bounds__(256, 2)
gemm_nt_bias(const float* __restrict__ A, const float* __restrict__ B,
             const float* __restrict__ bias, float* __restrict__ C,
             int N, int M, int K)
{
    __shared__ float As[2][8][128];
    __shared__ float Bs[2][8][128];

    const int tid  = threadIdx.x;
    const int lrow = tid >> 1;             // 0..127
    const int lcol = (tid & 1) << 2;       // 0 or 4
    const size_t arow = (size_t)blockIdx.y * 128 + lrow;
    const size_t brow = (size_t)blockIdx.x * 128 + lrow;
    const bool bval = brow < (size_t)M;

    const float* Ap = A + arow * (size_t)K + lcol;
    const float* Bp = B + brow * (size_t)K + lcol;

    const int ty = tid >> 4;
    const int tx = tid & 15;

    float acc[8][8];
#pragma unroll
    for (int i = 0; i < 8; i++)
#pragma unroll
        for (int j = 0; j < 8; j++) acc[i][j] = 0.f;

    // Preload first tile
    {
        float4 a4 = *(const float4*)(Ap);
        float4 b4 = bval ? *(const float4*)(Bp) : make_float4(0.f, 0.f, 0.f, 0.f);
        As[0][lcol + 0][lrow] = a4.x; As[0][lcol + 1][lrow] = a4.y;
        As[0][lcol + 2][lrow] = a4.z; As[0][lcol + 3][lrow] = a4.w;
        Bs[0][lcol + 0][lrow] = b4.x; Bs[0][lcol + 1][lrow] = b4.y;
        Bs[0][lcol + 2][lrow] = b4.z; Bs[0][lcol + 3][lrow] = b4.w;
    }
    __syncthreads();

    int buf = 0;
    for (int k0 = 8; k0 < K; k0 += 8) {
        // Prefetch next tile into registers
        float4 a4n = *(const float4*)(Ap + k0);
        float4 b4n = bval ? *(const float4*)(Bp + k0) : make_float4(0.f, 0.f, 0.f, 0.f);

        // Compute on current buffer
#pragma unroll
        for (int kk = 0; kk < 8; kk++) {
            const float4 a0 = *(const float4*)&As[buf][kk][ty * 8];
            const float4 a1 = *(const float4*)&As[buf][kk][ty * 8 + 4];
            const float4 b0 = *(const float4*)&Bs[buf][kk][tx * 8];
            const float4 b1 = *(const float4*)&Bs[buf][kk][tx * 8 + 4];
            const float ar[8] = {a0.x, a0.y, a0.z, a0.w, a1.x, a1.y, a1.z, a1.w};
            const float br[8] = {b0.x, b0.y, b0.z, b0.w, b1.x, b1.y, b1.z, b1.w};
#pragma unroll
            for (int i = 0; i < 8; i++)
#pragma unroll
                for (int j = 0; j < 8; j++) acc[i][j] = fmaf(ar[i], br[j], acc[i][j]);
        }

        // Store prefetched tile into the other buffer
        const int nb = buf ^ 1;
        As[nb][lcol + 0][lrow] = a4n.x; As[nb][lcol + 1][lrow] = a4n.y;
        As[nb][lcol + 2][lrow] = a4n.z; As[nb][lcol + 3][lrow] = a4n.w;
        Bs[nb][lcol + 0][lrow] = b4n.x; Bs[nb][lcol + 1][lrow] = b4n.y;
        Bs[nb][lcol + 2][lrow] = b4n.z; Bs[nb][lcol + 3][lrow] = b4n.w;
        __syncthreads();
        buf = nb;
    }

    // Last tile
#pragma unroll
    for (int kk = 0; kk < 8; kk++) {
        const float4 a0 = *(const float4*)&As[buf][kk][ty * 8];
        const float4 a1 = *(const float4*)&As[buf][kk][ty * 8 + 4];
        const float4 b0 = *(const float4*)&Bs[buf][kk][tx * 8];
        const float4 b1 = *(const float4*)&Bs[buf][kk][tx * 8 + 4];
        const float ar[8] = {a0.x, a0.y, a0.z, a0.w, a1.x, a1.y, a1.z, a1.w};
        const float br[8] = {b0.x, b0.y, b0.z, b0.w, b1.x, b1.y, b1.z, b1.w};
#pragma unroll
        for (int i = 0; i < 8; i++)
#pragma unroll
            for (int j = 0; j < 8; j++) acc[i][j] = fmaf(ar[i], br[j], acc[i][j]);
    }

    // Epilogue: bias + store (float4; M is a multiple of 4 so guard whole vec)
    const int colbase = blockIdx.x * 128 + tx * 8;
    const float4 bi0 = (colbase < M) ? *(const float4*)&bias[colbase]
                                     : make_float4(0.f, 0.f, 0.f, 0.f);
    const float4 bi1 = (colbase + 4 < M) ? *(const float4*)&bias[colbase + 4]
                                         : make_float4(0.f, 0.f, 0.f, 0.f);
#pragma unroll
    for (int i = 0; i < 8; i++) {
        const size_t row = (size_t)blockIdx.y * 128 + ty * 8 + i;
        if (colbase < M) {
            float4 o0 = make_float4(acc[i][0] + bi0.x, acc[i][1] + bi0.y,
                                    acc[i][2] + bi0.z, acc[i][3] + bi0.w);
            *(float4*)&C[row * (size_t)M + colbase] = o0;
        }
        if (colbase + 4 < M) {
            float4 o1 = make_float4(acc[i][4] + bi1.x, acc[i][5] + bi1.y,
                                    acc[i][6] + bi1.z, acc[i][7] + bi1.w);
            *(float4*)&C[row * (size_t)M + colbase + 4] = o1;
        }
    }
}

// ---------------------------------------------------------------------------
// Tiled sliding-window attention (flash style).
// ---------------------------------------------------------------------------
#define ATT_SMEM_FLOATS (4 * 64 * 64 + 3 * 64)

__global__ void __launch_bounds__(256)
attn_tile_kernel(const float* __restrict__ q, const float* __restrict__ k,
                 const float* __restrict__ v, float* __restrict__ o,
                 const int* __restrict__ winp)
{
    extern __shared__ float sm[];
    float* Qs  = sm;
    float* Kst = Qs + 64 * 64;
    float* Vs  = Kst + 64 * 64;
    float* Ss  = Vs + 64 * 64;
    float* m_s = Ss + 64 * 64;
    float* l_s = m_s + 64;
    float* sc_s = l_s + 64;

    const int q0 = blockIdx.x * 64;
    const int h  = blockIdx.y;
    const int b  = blockIdx.z;
    const int tid = threadIdx.x;
    const int win = *winp;

    const size_t base_q = ((size_t)(b * LL + q0)) * DD + h * HD;

    for (int i = tid; i < 1024; i += 256) {
        const int r = i >> 4;
        const int d4 = (i & 15) << 2;
        *(float4*)&Qs[r * 64 + d4] =
            *(const float4*)&q[base_q + (size_t)r * DD + d4];
    }
    if (tid < 64) { m_s[tid] = -INFINITY; l_s[tid] = 0.f; }

    const int ty = tid >> 4;
    const int tx = tid & 15;
    float accO[4][4];
#pragma unroll
    for (int i = 0; i < 4; i++)
#pragma unroll
        for (int j = 0; j < 4; j++) accO[i][j] = 0.f;

    int lo = q0 - win + 1;
    if (lo < 0) lo = 0;
    const int kt0 = lo >> 6;
    const int kt1 = q0 >> 6;

    __syncthreads();

    for (int kt = kt0; kt <= kt1; kt++) {
        const int j0 = kt << 6;
        const size_t base_k = ((size_t)(b * LL + j0)) * DD + h * HD;

        for (int i = tid; i < 1024; i += 256) {
            const int r = i >> 4;
            const int d4 = (i & 15) << 2;
            const float4 kv = *(const float4*)&k[base_k + (size_t)r * DD + d4];
            Kst[(d4 + 0) * 64 + r] = kv.x;
            Kst[(d4 + 1) * 64 + r] = kv.y;
            Kst[(d4 + 2) * 64 + r] = kv.z;
            Kst[(d4 + 3) * 64 + r] = kv.w;
            *(float4*)&Vs[r * 64 + d4] =
                *(const float4*)&v[base_k + (size_t)r * DD + d4];
        }
        __syncthreads();

        float accS[4][4];
#pragma unroll
        for (int i = 0; i < 4; i++)
#pragma unroll
            for (int j = 0; j < 4; j++) accS[i][j] = 0.f;

        for (int d = 0; d < 64; d += 4) {
            float4 qv[4];
#pragma unroll
            for (int i = 0; i < 4; i++)
                qv[i] = *(const float4*)&Qs[(ty * 4 + i) * 64 + d];
#pragma unroll
            for (int dd = 0; dd < 4; dd++) {
                const float4 kv = *(const float4*)&Kst[(d + dd) * 64 + tx * 4];
#pragma unroll
                for (int i = 0; i < 4; i++) {
                    const float qq = ((const float*)&qv[i])[dd];
                    accS[i][0] = fmaf(qq, kv.x, accS[i][0]);
                    accS[i][1] = fmaf(qq, kv.y, accS[i][1]);
                    accS[i][2] = fmaf(qq, kv.z, accS[i][2]);
                    accS[i][3] = fmaf(qq, kv.w, accS[i][3]);
                }
            }
        }

#pragma unroll
        for (int i = 0; i < 4; i++) {
            const int qi = q0 + ty * 4 + i;
#pragma unroll
            for (int j = 0; j < 4; j++) {
                const int jj = j0 + tx * 4 + j;
                const bool ok = (jj <= qi) && (qi - jj < win);
                Ss[(ty * 4 + i) * 64 + tx * 4 + j] =
                    ok ? accS[i][j] * 0.125f : -INFINITY;
            }
        }
        __syncthreads();

        {
            const int row = tid >> 2;
            const int part = tid & 3;
            float* srow = &Ss[row * 64 + part * 16];
            float tm = -INFINITY;
#pragma unroll
            for (int c = 0; c < 16; c++) tm = fmaxf(tm, srow[c]);
            tm = fmaxf(tm, __shfl_xor_sync(0xffffffffu, tm, 1));
            tm = fmaxf(tm, __shfl_xor_sync(0xffffffffu, tm, 2));

            const float mold = m_s[row];
            const float nm = fmaxf(mold, tm);
            float scale;
            float psum = 0.f;
            if (nm == -INFINITY) {
                scale = 1.f;
#pragma unroll
                for (int c = 0; c < 16; c++) srow[c] = 0.f;
            } else {
                scale = expf(mold - nm);
#pragma unroll
                for (int c = 0; c < 16; c++) {
                    const float p = expf(srow[c] - nm);
                    srow[c] = p;
                    psum += p;
                }
            }
            psum += __shfl_xor_sync(0xffffffffu, psum, 1);
            psum += __shfl_xor_sync(0xffffffffu, psum, 2);
            if (part == 0) {
                m_s[row] = nm;
                l_s[row] = l_s[row] * scale + psum;
                sc_s[row] = scale;
            }
        }
        __syncthreads();

#pragma unroll
        for (int i = 0; i < 4; i++) {
            const float s = sc_s[ty * 4 + i];
#pragma unroll
            for (int j = 0; j < 4; j++) accO[i][j] *= s;
        }
        for (int kk = 0; kk < 64; kk += 4) {
            float4 pv[4];
#pragma unroll
            for (int i = 0; i < 4; i++)
                pv[i] = *(const float4*)&Ss[(ty * 4 + i) * 64 + kk];
#pragma unroll
            for (int dd = 0; dd < 4; dd++) {
                const float4 vv = *(const float4*)&Vs[(kk + dd) * 64 + tx * 4];
#pragma unroll
                for (int i = 0; i < 4; i++) {
                    const float pp = ((const float*)&pv[i])[dd];
                    accO[i][0] = fmaf(pp, vv.x, accO[i][0]);
                    accO[i][1] = fmaf(pp, vv.y, accO[i][1]);
                    accO[i][2] = fmaf(pp, vv.z, accO[i][2]);
                    accO[i][3] = fmaf(pp, vv.w, accO[i][3]);
                }
            }
        }
        __syncthreads();
    }

#pragma unroll
    for (int i = 0; i < 4; i++) {
        const int r = ty * 4 + i;
        const float linv = 1.f / l_s[r];
#pragma unroll
        for (int j = 0; j < 4; j++) {
            float outv = accO[i][j] * linv;
            if (!isfinite(outv)) outv = 0.f;
            o[((size_t)(b * LL + q0 + r)) * DD + h * HD + tx * 4 + j] = outv;
        }
    }
}

// ---------------------------------------------------------------------------
// g = silu(z1) * z3
// ---------------------------------------------------------------------------
__global__ void silu_mul_k(const float* __restrict__ z1,
                           const float* __restrict__ z3,
                           float* __restrict__ g, size_t n)
{
    size_t i = (size_t)blockIdx.x * blockDim.x + threadIdx.x;
    if (i < n) {
        float a = z1[i];
        float sv = a / (1.f + expf(-a));
        g[i] = sv * z3[i];
    }
}

// ---------------------------------------------------------------------------
// Launch
// ---------------------------------------------------------------------------
extern "C" void kernel_launch(void* const* d_in, const int* in_sizes, int n_in,
                              void* d_out, int out_size)
{
    const float* x    = (const float*)d_in[0];
    const float* wq_w = (const float*)d_in[1];
    const float* wq_b = (const float*)d_in[2];
    const float* wk_w = (const float*)d_in[3];
    const float* wk_b = (const float*)d_in[4];
    const float* wv_w = (const float*)d_in[5];
    const float* wv_b = (const float*)d_in[6];
    const float* wo_w = (const float*)d_in[7];
    const float* wo_b = (const float*)d_in[8];
    const float* q_nw = (const float*)d_in[9];
    const float* k_nw = (const float*)d_in[10];
    const float* s_nw = (const float*)d_in[11];
    const float* sp_nw= (const float*)d_in[12];
    const float* f_nw = (const float*)d_in[13];
    const float* fp_nw= (const float*)d_in[14];
    const float* w1_w = (const float*)d_in[15];
    const float* w1_b = (const float*)d_in[16];
    const float* w2_w = (const float*)d_in[17];
    const float* w2_b = (const float*)d_in[18];
    const float* w3_w = (const float*)d_in[19];
    const float* w3_b = (const float*)d_in[20];
    const int*   winp = (const int*)d_in[21];

    float* base = nullptr;
    cudaGetSymbolAddress((void**)&base, g_scratch);
    float* xn   = base + 0 * SZ_D;
    float* q    = base + 1 * SZ_D;
    float* k    = base + 2 * SZ_D;
    float* v    = base + 3 * SZ_D;
    float* attn = base + 4 * SZ_D;
    float* a    = base + 5 * SZ_D;
    float* h    = base + 6 * SZ_D;
    float* hn   = base + 7 * SZ_D;
    float* f    = base + 8 * SZ_D;
    float* z1   = base + 9 * SZ_D;
    float* z3   = base + 9 * SZ_D + SZ_I;

    float* out = (float*)d_out;

    rmsnorm_k<DD, 256><<<NROWS, 256>>>(x, s_nw, nullptr, xn);

    {
        dim3 grid(DD / 128, NROWS / 128);
        gemm_nt_bias<<<grid, 256>>>(xn, wq_w, wq_b, q, NROWS, DD, DD);
        gemm_nt_bias<<<grid, 256>>>(xn, wk_w, wk_b, k, NROWS, DD, DD);
        gemm_nt_bias<<<grid, 256>>>(xn, wv_w, wv_b, v, NROWS, DD, DD);
    }

    rmsnorm_k<HD, 64><<<NROWS * HH, 64>>>(q, q_nw, nullptr, q);
    rmsnorm_k<HD, 64><<<NROWS * HH, 64>>>(k, k_nw, nullptr, k);

    {
        const size_t smem_bytes = (size_t)ATT_SMEM_FLOATS * sizeof(float);
        cudaFuncSetAttribute(attn_tile_kernel,
                             cudaFuncAttributeMaxDynamicSharedMemorySize,
                             (int)smem_bytes);
        dim3 grid(LL / 64, HH, BB);
        attn_tile_kernel<<<grid, 256, smem_bytes>>>(q, k, v, attn, winp);
    }

    {
        dim3 grid(DD / 128, NROWS / 128);
        gemm_nt_bias<<<grid, 256>>>(attn, wo_w, wo_b, a, NROWS, DD, DD);
    }

    rmsnorm_k<DD, 256><<<NROWS, 256>>>(a, sp_nw, x, h);
    rmsnorm_k<DD, 256><<<NROWS, 256>>>(h, f_nw, nullptr, hn);

    {
        dim3 grid((II + 127) / 128, NROWS / 128);
        gemm_nt_bias<<<grid, 256>>>(hn, w1_w, w1_b, z1, NROWS, II, DD);
        gemm_nt_bias<<<grid, 256>>>(hn, w3_w, w3_b, z3, NROWS, II, DD);
    }

    {
        size_t n = (size_t)NROWS * II;
        silu_mul_k<<<(int)((n + 255) / 256), 256>>>(z1, z3, z1, n);
    }

    {
        dim3 grid(DD / 128, NROWS / 128);
        gemm_nt_bias<<<grid, 256>>>(z1, w2_w, w2_b, f, NROWS, DD, II);
    }

    rmsnorm_k<DD, 256><<<NROWS, 256>>>(f, fp_nw, h, out);
}